// round 5
// baseline (speedup 1.0000x reference)
#include <cuda_runtime.h>
#include <cuda_bf16.h>
#include <math.h>
#include <stdint.h>

#define BB 1024
#define DD 64
#define HH 128
#define NKS 4          // K=64 -> 4 k-steps of 16 (bf16 mma)
#define JT 32          // j-tile
#define IB 2           // i's per CTA
#define NBLK (BB / JT) // 32 j-blocks
#define ASTR 36        // A smem row stride in u32 words (conflict-free)
#define TSTR 132       // T2 smem row stride (words)

// Scratch (allocation-free rule: __device__ globals)
__device__ __align__(16) float g_T1[BB * HH];
__device__ __align__(16) float g_T2[BB * HH];
__device__ __align__(16) float g_S[BB * HH];
__device__ float g_tau[BB];

__device__ __forceinline__ uint32_t pack_bf2(float lo, float hi) {
  __nv_bfloat162 v = __floats2bfloat162_rn(lo, hi);
  return *(uint32_t*)&v;
}

__device__ __forceinline__ void mma16(float* c, uint32_t a0, uint32_t a1,
                                      uint32_t a2, uint32_t a3, uint32_t b0,
                                      uint32_t b1) {
  asm volatile(
      "mma.sync.aligned.m16n8k16.row.col.f32.bf16.bf16.f32 "
      "{%0,%1,%2,%3},{%4,%5,%6,%7},{%8,%9},{%0,%1,%2,%3};"
      : "+f"(c[0]), "+f"(c[1]), "+f"(c[2]), "+f"(c[3])
      : "r"(a0), "r"(a1), "r"(a2), "r"(a3), "r"(b0), "r"(b1));
}

__device__ __forceinline__ void cp16(uint32_t smem_dst, const void* gsrc) {
  asm volatile("cp.async.cg.shared.global [%0], [%1], 16;" ::"r"(smem_dst),
               "l"(gsrc)
               : "memory");
}

// ---------------------------------------------------------------------------
// Kernel 1: per-row precompute + zero g_S
// ---------------------------------------------------------------------------
__global__ __launch_bounds__(HH) void precompute_kernel(
    const float* __restrict__ x, const float* __restrict__ W1,
    const float* __restrict__ b1, const float* __restrict__ Wt,
    const float* __restrict__ bt) {
  __shared__ float xi[DD];
  const int i = blockIdx.x;
  const int h = threadIdx.x;
  if (h < DD) xi[h] = x[i * DD + h];
  g_S[i * HH + h] = 0.f;
  __syncthreads();

  float ai = 0.f, aj = 0.f, ad = 0.f;
#pragma unroll 8
  for (int d = 0; d < DD; ++d) {
    const float xv = xi[d];
    ai += xv * W1[d * HH + h];
    aj += xv * W1[(DD + d) * HH + h];
    ad += xv * W1[(2 * DD + d) * HH + h];
  }
  g_T1[i * HH + h] = ai + ad + b1[h];
  g_T2[i * HH + h] = aj - ad;

  if (h == 0) {
    float z = bt[0];
#pragma unroll 8
    for (int d = 0; d < DD; ++d) z += xi[d] * Wt[d];
    const float sp = (z > 20.f) ? z : log1pf(expf(z));
    g_tau[i] = fmaxf(sp, 0.01f) + 1.0f;
  }
}

// ---------------------------------------------------------------------------
// Kernel 2: symmetric bf16 pair-GEMM, software-pipelined (1 sync / tile).
// CTA c: i-pair p=c>>1 (i0=2p), half c&1; tiles ti = b+half, +2, ... (b=i0>>5)
// Normal orientation -> register sacc (atomicAdd flush at end).
// Transpose orientation (ti != b) -> atomicAdd to g_S[j], T1[j] read from gmem.
// ---------------------------------------------------------------------------
__global__ __launch_bounds__(256, 2) void pair_kernel(
    const float* __restrict__ x, const float* __restrict__ W1) {
  __shared__ __align__(16) float xs[IB][DD];
  __shared__ __align__(16) uint32_t As[2][IB][JT * ASTR];  // bf16x2, dbl-buf
  __shared__ __align__(16) float t2s[JT * TSTR];           // single, cp.async

  const int t = threadIdx.x;
  const int w = t >> 5, lane = t & 31;
  const int wr = w >> 2, wc = w & 3;
  const int g = lane >> 2, tig = lane & 3;
  const int p = blockIdx.x >> 1;
  const int half = blockIdx.x & 1;
  const int i0 = p * IB;
  const int b = i0 >> 5;

  if (t < IB * DD) ((float*)xs)[t] = x[(size_t)i0 * DD + t];

  // B fragments (Wab) -> bf16x2 registers
  uint32_t Bv[NKS][4][2];
#pragma unroll
  for (int ks = 0; ks < NKS; ks++)
#pragma unroll
    for (int nt = 0; nt < 4; nt++) {
      const int n = wc * 32 + nt * 8 + g;
#pragma unroll
      for (int hf = 0; hf < 2; hf++) {
        const int k = ks * 16 + 2 * tig + hf * 8;
        Bv[ks][nt][hf] = pack_bf2(W1[(size_t)(3 * DD + k) * HH + n],
                                  W1[(size_t)(3 * DD + k + 1) * HH + n]);
      }
    }

  float2 t1iv[IB][4], t2iv[IB][4];
#pragma unroll
  for (int ii = 0; ii < IB; ii++)
#pragma unroll
    for (int nt = 0; nt < 4; nt++) {
      const size_t off = (size_t)(i0 + ii) * HH + wc * 32 + nt * 8 + 2 * tig;
      t1iv[ii][nt] = *(const float2*)&g_T1[off];
      t2iv[ii][nt] = *(const float2*)&g_T2[off];
    }

  float sacc[IB][8];
#pragma unroll
  for (int a = 0; a < IB; a++)
#pragma unroll
    for (int q = 0; q < 8; q++) sacc[a][q] = 0.f;

  const int ar = wr * 16 + g;
  // per-thread staging coords (A-build / xj prefetch): e = t + r*256
  const int arow0 = t >> 4, acg = t & 15;  // r=0 row; r=1 row = arow0+16
  const uint32_t t2s_base = (uint32_t)__cvta_generic_to_shared(t2s);
  const int t2j = t >> 5, t2q = (t & 31) << 2;  // r adds 8 rows

  const int ti0 = b + half;
  __syncthreads();  // xs visible

  if (ti0 < NBLK) {
    float4 xjp[2];
    // prologue: prefetch + build As[0] for tile ti0
#pragma unroll
    for (int r = 0; r < 2; r++)
      xjp[r] =
          *(const float4*)&x[(size_t)(ti0 * JT + arow0 + r * 16) * DD + acg * 4];
#pragma unroll
    for (int r = 0; r < 2; r++) {
      const int row = arow0 + r * 16;
#pragma unroll
      for (int ii = 0; ii < IB; ii++) {
        const float4 xi4 = *(const float4*)&xs[ii][acg * 4];
        uint2 o;
        o.x = pack_bf2(fabsf(xjp[r].x - xi4.x), fabsf(xjp[r].y - xi4.y));
        o.y = pack_bf2(fabsf(xjp[r].z - xi4.z), fabsf(xjp[r].w - xi4.w));
        *(uint2*)&As[0][ii][row * ASTR + acg * 2] = o;
      }
    }
    __syncthreads();

    int cur = 0;
    for (int ti = ti0; ti < NBLK; ti += 2) {
      const int j0 = ti * JT;
      const bool diag = (ti == b);
      const int tin = ti + 2;

      // stage T2 tile (this tile) via cp.async — overlaps the MMAs below
#pragma unroll
      for (int r = 0; r < 4; r++) {
        const int j = t2j + r * 8;
        cp16(t2s_base + (uint32_t)(j * TSTR + t2q) * 4,
             &g_T2[(size_t)(j0 + j) * HH + t2q]);
      }
      asm volatile("cp.async.commit_group;" ::: "memory");

      // prefetch x_j for next tile
      if (tin < NBLK) {
#pragma unroll
        for (int r = 0; r < 2; r++)
          xjp[r] = *(const float4*)&x[(size_t)(tin * JT + arow0 + r * 16) * DD +
                                      acg * 4];
      }

      float tracc[4][4];
#pragma unroll
      for (int nt = 0; nt < 4; nt++)
#pragma unroll
        for (int q = 0; q < 4; q++) tracc[nt][q] = 0.f;

      bool waited = false;
#pragma unroll
      for (int ii = 0; ii < IB; ii++) {
        float cc[4][4];
#pragma unroll
        for (int nt = 0; nt < 4; nt++)
#pragma unroll
          for (int q = 0; q < 4; q++) cc[nt][q] = 0.f;

#pragma unroll
        for (int ks = 0; ks < NKS; ks++) {
          const uint32_t a0 = As[cur][ii][ar * ASTR + ks * 8 + tig];
          const uint32_t a1 = As[cur][ii][(ar + 8) * ASTR + ks * 8 + tig];
          const uint32_t a2 = As[cur][ii][ar * ASTR + ks * 8 + tig + 4];
          const uint32_t a3 = As[cur][ii][(ar + 8) * ASTR + ks * 8 + tig + 4];
#pragma unroll
          for (int nt = 0; nt < 4; nt++)
            mma16(cc[nt], a0, a1, a2, a3, Bv[ks][nt][0], Bv[ks][nt][1]);
        }

        if (!waited) {  // T2 tile must be in smem before first epilogue
          asm volatile("cp.async.wait_group 0;" ::: "memory");
          waited = true;
        }

        // normal: S[i] += relu(D + T1[i] + T2[j])
#pragma unroll
        for (int nt = 0; nt < 4; nt++) {
          const int h0 = wc * 32 + nt * 8 + 2 * tig;
          const float2 ta = *(const float2*)&t2s[ar * TSTR + h0];
          const float2 tb = *(const float2*)&t2s[(ar + 8) * TSTR + h0];
          const float2 t1 = t1iv[ii][nt];
          sacc[ii][nt * 2 + 0] += fmaxf(cc[nt][0] + t1.x + ta.x, 0.f) +
                                  fmaxf(cc[nt][2] + t1.x + tb.x, 0.f);
          sacc[ii][nt * 2 + 1] += fmaxf(cc[nt][1] + t1.y + ta.y, 0.f) +
                                  fmaxf(cc[nt][3] + t1.y + tb.y, 0.f);
        }
        // transpose: S[j] += relu(D + T1[j] + T2[i]); T1[j] direct from gmem
        if (!diag) {
#pragma unroll
          for (int nt = 0; nt < 4; nt++) {
            const int h0 = wc * 32 + nt * 8 + 2 * tig;
            const float2 ja =
                *(const float2*)&g_T1[(size_t)(j0 + ar) * HH + h0];
            const float2 jb =
                *(const float2*)&g_T1[(size_t)(j0 + ar + 8) * HH + h0];
            const float2 t2 = t2iv[ii][nt];
            tracc[nt][0] += fmaxf(cc[nt][0] + ja.x + t2.x, 0.f);
            tracc[nt][1] += fmaxf(cc[nt][1] + ja.y + t2.y, 0.f);
            tracc[nt][2] += fmaxf(cc[nt][2] + jb.x + t2.x, 0.f);
            tracc[nt][3] += fmaxf(cc[nt][3] + jb.y + t2.y, 0.f);
          }
        }
      }

      if (!diag) {
#pragma unroll
        for (int nt = 0; nt < 4; nt++) {
          const int h0 = wc * 32 + nt * 8 + 2 * tig;
          atomicAdd(&g_S[(size_t)(j0 + ar) * HH + h0 + 0], tracc[nt][0]);
          atomicAdd(&g_S[(size_t)(j0 + ar) * HH + h0 + 1], tracc[nt][1]);
          atomicAdd(&g_S[(size_t)(j0 + ar + 8) * HH + h0 + 0], tracc[nt][2]);
          atomicAdd(&g_S[(size_t)(j0 + ar + 8) * HH + h0 + 1], tracc[nt][3]);
        }
      }

      // build next A tile from prefetched regs into the other buffer
      if (tin < NBLK) {
#pragma unroll
        for (int r = 0; r < 2; r++) {
          const int row = arow0 + r * 16;
#pragma unroll
          for (int ii = 0; ii < IB; ii++) {
            const float4 xi4 = *(const float4*)&xs[ii][acg * 4];
            uint2 o;
            o.x = pack_bf2(fabsf(xjp[r].x - xi4.x), fabsf(xjp[r].y - xi4.y));
            o.y = pack_bf2(fabsf(xjp[r].z - xi4.z), fabsf(xjp[r].w - xi4.w));
            *(uint2*)&As[cur ^ 1][ii][row * ASTR + acg * 2] = o;
          }
        }
      }
      __syncthreads();  // A build visible; t2s/epilogue reads done
      cur ^= 1;
    }
  }

  // Flush normal-orientation sacc
#pragma unroll
  for (int a = 0; a < IB; a++)
#pragma unroll
    for (int q = 0; q < 8; q++) {
      float v = sacc[a][q];
      v += __shfl_xor_sync(0xffffffffu, v, 4);
      v += __shfl_xor_sync(0xffffffffu, v, 8);
      v += __shfl_xor_sync(0xffffffffu, v, 16);
      sacc[a][q] = v;
    }
  if (lane < 4) {
#pragma unroll
    for (int a = 0; a < IB; a++)
#pragma unroll
      for (int nt = 0; nt < 4; nt++) {
        const int h0 = wc * 32 + nt * 8 + 2 * lane;
        atomicAdd(&g_S[(size_t)(i0 + a) * HH + h0 + 0], sacc[a][nt * 2 + 0]);
        atomicAdd(&g_S[(size_t)(i0 + a) * HH + h0 + 1], sacc[a][nt * 2 + 1]);
      }
  }
}

// ---------------------------------------------------------------------------
// Kernel 3: head + layernorm per row
// ---------------------------------------------------------------------------
__global__ __launch_bounds__(HH) void head_kernel(
    const float* __restrict__ x, const float* __restrict__ W2,
    const float* __restrict__ b2, const float* __restrict__ Wa,
    const float* __restrict__ ba, const float* __restrict__ Wr,
    const float* __restrict__ br, const float* __restrict__ gamma,
    const float* __restrict__ beta, float* __restrict__ out) {
  __shared__ float S_s[HH], hm_s[HH], xi[DD];
  __shared__ float red[4];
  const int i = blockIdx.x;
  const int t = threadIdx.x;
  const int w = t >> 5, lane = t & 31;

  if (t < DD) xi[t] = x[i * DD + t];
  S_s[t] = g_S[(size_t)i * HH + t] * (1.0f / BB);
  __syncthreads();

  float acc = b2[t];
#pragma unroll 8
  for (int k = 0; k < HH; ++k) acc += S_s[k] * W2[k * HH + t];
  hm_s[t] = acc / g_tau[i];
  __syncthreads();

  float acc2 = ba[t];
#pragma unroll 8
  for (int k = 0; k < HH; ++k) acc2 += hm_s[k] * Wa[k * HH + t];
  const float hv = fmaxf(acc2, 0.f);
  float a3 = br[t];
#pragma unroll 8
  for (int d = 0; d < DD; ++d) a3 += xi[d] * Wr[d * HH + t];
  const float yv = hv + a3;

  float v = yv;
#pragma unroll
  for (int off = 16; off > 0; off >>= 1) v += __shfl_xor_sync(0xffffffffu, v, off);
  if (lane == 0) red[w] = v;
  __syncthreads();
  const float mu = (red[0] + red[1] + red[2] + red[3]) * (1.0f / HH);
  __syncthreads();
  const float dv = yv - mu;
  float v2 = dv * dv;
#pragma unroll
  for (int off = 16; off > 0; off >>= 1) v2 += __shfl_xor_sync(0xffffffffu, v2, off);
  if (lane == 0) red[w] = v2;
  __syncthreads();
  const float var = (red[0] + red[1] + red[2] + red[3]) * (1.0f / HH);

  out[(size_t)i * HH + t] = dv * rsqrtf(var + 1e-5f) * gamma[t] + beta[t];
}

// ---------------------------------------------------------------------------
// Inputs: 0:x 1:W1 2:b1 3:W2 4:b2 5:Wt 6:bt 7:Wa 8:ba 9:Wr 10:br 11:gamma 12:beta
// ---------------------------------------------------------------------------
extern "C" void kernel_launch(void* const* d_in, const int* in_sizes, int n_in,
                              void* d_out, int out_size) {
  const float* x     = (const float*)d_in[0];
  const float* W1    = (const float*)d_in[1];
  const float* b1    = (const float*)d_in[2];
  const float* W2    = (const float*)d_in[3];
  const float* b2    = (const float*)d_in[4];
  const float* Wt    = (const float*)d_in[5];
  const float* bt    = (const float*)d_in[6];
  const float* Wa    = (const float*)d_in[7];
  const float* ba    = (const float*)d_in[8];
  const float* Wr    = (const float*)d_in[9];
  const float* br    = (const float*)d_in[10];
  const float* gamma = (const float*)d_in[11];
  const float* beta  = (const float*)d_in[12];
  float* out = (float*)d_out;

  precompute_kernel<<<BB, HH>>>(x, W1, b1, Wt, bt);
  pair_kernel<<<BB, 256>>>(x, W1);
  head_kernel<<<BB, HH>>>(x, W2, b2, Wa, ba, Wr, br, gamma, beta, out);
}

// round 7
// speedup vs baseline: 1.5857x; 1.5857x over previous
#include <cuda_runtime.h>
#include <cuda_bf16.h>
#include <math.h>
#include <stdint.h>

#define BB 1024
#define DD 64
#define HH 128
#define IB 4            // i's per CTA
#define MT 128          // j's per tile
#define THREADS 256

#if defined(__CUDA_ARCH_FEAT_SM103_ALL) || defined(__CUDA_ARCH_FEAT_SM100_ALL) || \
    defined(__CUDA_ARCH_FEAT_SM101_ALL)
#define HAS_TCGEN05 1
#else
#define HAS_TCGEN05 0
#endif

// dynamic smem layout (bytes)
#define OFF_A     0          // Wab^T bf16 [128 x 64], SW128, 16384
#define OFF_B     16384      // 2 x |delta| bf16 [128 x 64], SW128, 32768
#define OFF_XJ    49152      // x_j tile f32 [128 x 64], 32768
#define OFF_T2    81920      // 2 x T2 chunk f32 [32 x 128], 32768
#define OFF_XI    114688     // x_i f32 [4 x 64], 1024
#define OFF_SC    115712     // S partials f32 [4][2][128], 4096
#define OFF_MBAR  119808
#define OFF_TPTR  119816
#define SMEM_TOTAL 119840

// idesc: dtype=F32, a=BF16, b=BF16, N=128, M=128
#define IDESC ((1u << 4) | (1u << 7) | (1u << 10) | ((HH / 8) << 17) | ((MT / 16) << 24))

// Scratch
__device__ __align__(16) float g_T1[BB * HH];
__device__ __align__(16) float g_T2[BB * HH];
__device__ __align__(16) float g_S[BB * HH];
__device__ float g_tau[BB];

__device__ __forceinline__ uint32_t pack_bf2(float lo, float hi) {
  __nv_bfloat162 v = __floats2bfloat162_rn(lo, hi);
  return *(uint32_t*)&v;
}
__device__ __forceinline__ uint32_t sw128(uint32_t o) {
  return o ^ ((o >> 3) & 0x70);
}
__device__ __forceinline__ uint64_t smem_desc(uint32_t addr) {
  // SW128, version=1 (Blackwell), SBO=64, LBO=1
  return (2ull << 61) | (1ull << 46) | (64ull << 32) | (1ull << 16) |
         ((uint64_t)(addr >> 4) & 0x3FFF);
}
__device__ __forceinline__ void cp16(uint32_t smem_dst, const void* gsrc) {
  asm volatile("cp.async.cg.shared.global [%0], [%1], 16;" ::"r"(smem_dst),
               "l"(gsrc)
               : "memory");
}

#if HAS_TCGEN05
__device__ __forceinline__ void mma_f16_ss(uint32_t d, uint64_t ad, uint64_t bd,
                                           uint32_t idesc, bool accum) {
  uint32_t en = accum ? 1u : 0u;
  asm volatile(
      "{\n\t.reg .pred p;\n\tsetp.ne.u32 p, %5, 0;\n\t"
      "tcgen05.mma.cta_group::1.kind::f16 [%0], %1, %2, %3, {%4,%4,%4,%4}, "
      "p;\n\t}"
      :: "r"(d), "l"(ad), "l"(bd), "r"(idesc), "r"(0u), "r"(en)
      : "memory");
}
__device__ __forceinline__ void mbar_wait(uint32_t mbar, int parity) {
  asm volatile(
      "{\n\t.reg .pred P;\n\t"
      "WL%=:\n\t"
      "mbarrier.try_wait.parity.acquire.cta.shared::cta.b64 P, [%0], %1, "
      "0x989680;\n\t"
      "@P bra WD%=;\n\t"
      "bra WL%=;\n\t"
      "WD%=:\n\t}"
      :: "r"(mbar), "r"((uint32_t)parity)
      : "memory");
}
#define LDTM_X16(r, a)                                                       \
  asm volatile(                                                              \
      "tcgen05.ld.sync.aligned.32x32b.x16.b32 "                              \
      "{%0,%1,%2,%3,%4,%5,%6,%7,%8,%9,%10,%11,%12,%13,%14,%15}, [%16];"      \
      : "=r"((r)[0]), "=r"((r)[1]), "=r"((r)[2]), "=r"((r)[3]),              \
        "=r"((r)[4]), "=r"((r)[5]), "=r"((r)[6]), "=r"((r)[7]),              \
        "=r"((r)[8]), "=r"((r)[9]), "=r"((r)[10]), "=r"((r)[11]),            \
        "=r"((r)[12]), "=r"((r)[13]), "=r"((r)[14]), "=r"((r)[15])           \
      : "r"(a))
#endif  // HAS_TCGEN05

// ---------------------------------------------------------------------------
// Kernel 1: per-row precompute + zero g_S. 8 i's per CTA share W1 reads.
// ---------------------------------------------------------------------------
__global__ __launch_bounds__(HH) void precompute_kernel(
    const float* __restrict__ x, const float* __restrict__ W1,
    const float* __restrict__ b1, const float* __restrict__ Wt,
    const float* __restrict__ bt) {
  __shared__ float xi[8][DD];
  const int i0 = blockIdx.x * 8;
  const int h = threadIdx.x;
#pragma unroll
  for (int r = 0; r < 4; r++)
    ((float*)xi)[h + r * HH] = x[(size_t)i0 * DD + h + r * HH];
#pragma unroll
  for (int r = 0; r < 8; r++) g_S[(size_t)(i0 + r) * HH + h] = 0.f;
  __syncthreads();

  float ai[8], aj[8], ad[8];
#pragma unroll
  for (int r = 0; r < 8; r++) ai[r] = aj[r] = ad[r] = 0.f;
#pragma unroll 4
  for (int d = 0; d < DD; ++d) {
    const float w_i = W1[d * HH + h];
    const float w_j = W1[(DD + d) * HH + h];
    const float w_d = W1[(2 * DD + d) * HH + h];
#pragma unroll
    for (int r = 0; r < 8; r++) {
      const float xv = xi[r][d];
      ai[r] += xv * w_i;
      aj[r] += xv * w_j;
      ad[r] += xv * w_d;
    }
  }
  const float b1h = b1[h];
#pragma unroll
  for (int r = 0; r < 8; r++) {
    g_T1[(size_t)(i0 + r) * HH + h] = ai[r] + ad[r] + b1h;
    g_T2[(size_t)(i0 + r) * HH + h] = aj[r] - ad[r];
  }
  if (h < 8) {
    float z = bt[0];
#pragma unroll 8
    for (int d = 0; d < DD; ++d) z += xi[h][d] * Wt[d];
    const float sp = (z > 20.f) ? z : log1pf(expf(z));
    g_tau[i0 + h] = fmaxf(sp, 0.01f) + 1.0f;
  }
}

// ---------------------------------------------------------------------------
// Kernel 2: tcgen05 pair-GEMM, transposed: D[h][j] = Wab^T @ |x_i - x_j|^T.
// CTA c: i-group ig=c>>1 (i0=4*ig), j-half jh=c&1 (4 tiles of 128 j).
// Epilogue: warp w -> h = (w&3)*32+lane (TMEM subpartition = w%4),
// col-half ch = w>>2; j-reduction thread-local; one atomicAdd per (i,h).
// ---------------------------------------------------------------------------
__global__ __launch_bounds__(THREADS)
void pair_kernel(const float* __restrict__ x, const float* __restrict__ W1) {
#if HAS_TCGEN05
  extern __shared__ __align__(16) char smem[];
  float* xjs = (float*)(smem + OFF_XJ);
  float* t2c = (float*)(smem + OFF_T2);  // [2][32*128]
  float* xi = (float*)(smem + OFF_XI);   // [4][64]
  float* Sc = (float*)(smem + OFF_SC);   // [4][2][128]
  const uint32_t su = (uint32_t)__cvta_generic_to_shared(smem);

  const int t = threadIdx.x;
  const int w = t >> 5, lane = t & 31;
  const int sub = w & 3, ch = w >> 2;
  const int h = sub * 32 + lane;
  const int ig = blockIdx.x >> 1, jh = blockIdx.x & 1;
  const int i0 = ig * IB;

  if (w == 0) {
    asm volatile(
        "tcgen05.alloc.cta_group::1.sync.aligned.shared::cta.b32 [%0], %1;"
        :: "r"(su + OFF_TPTR), "r"(512u)
        : "memory");
    asm volatile("tcgen05.relinquish_alloc_permit.cta_group::1.sync.aligned;");
  }
  if (t == 0) {
    asm volatile("mbarrier.init.shared.b64 [%0], %1;" ::"r"(su + OFF_MBAR),
                 "r"(1u)
                 : "memory");
  }
  __syncthreads();
  uint32_t tmem;
  asm volatile("ld.shared.b32 %0, [%1];" : "=r"(tmem) : "r"(su + OFF_TPTR));

  // Build A = Wab^T (bf16, SW128): A[m=h][k] = W1[(192+k)*128 + m]
#pragma unroll
  for (int r = 0; r < 16; r++) {
    const int e = t + r * 256;  // 4096 bf16x2
    const int m = e >> 5, kp = e & 31, k = kp * 2;
    const uint32_t so = sw128((uint32_t)(m * 128 + kp * 4));
    *(uint32_t*)(smem + OFF_A + so) = pack_bf2(
        W1[(size_t)(3 * DD + k) * HH + m], W1[(size_t)(3 * DD + k + 1) * HH + m]);
  }
  if (t < IB * DD) xi[t] = x[(size_t)i0 * DD + t];

  float t1v[IB], acc[IB];
#pragma unroll
  for (int ii = 0; ii < IB; ii++) {
    t1v[ii] = g_T1[(size_t)(i0 + ii) * HH + h];
    acc[ii] = 0.f;
  }

  int ph = 0;
  const uint64_t adesc = smem_desc(su + OFF_A);

  for (int tt = 0; tt < 4; tt++) {
    const int j0 = (jh * 4 + tt) * MT;

    // stage x_j tile (32KB) + T2 chunk 0 (16KB) via cp.async
#pragma unroll
    for (int r = 0; r < 8; r++) {
      const int e = t + r * 256;
      const int j = e >> 4, sg = e & 15;
      cp16(su + OFF_XJ + (uint32_t)(j * 64 + sg * 4) * 4,
           &x[(size_t)(j0 + j) * DD + sg * 4]);
    }
#pragma unroll
    for (int r = 0; r < 4; r++) {
      const int e = t + r * 256;
      const int j = e >> 5, sg = e & 31;
      cp16(su + OFF_T2 + (uint32_t)(j * 128 + sg * 4) * 4,
           &g_T2[(size_t)(j0 + j) * HH + sg * 4]);
    }
    asm volatile("cp.async.commit_group;" ::: "memory");
    asm volatile("cp.async.wait_group 0;" ::: "memory");
    __syncthreads();

    // 2 rounds x 2 B tiles -> 16 MMAs
#pragma unroll
    for (int rd = 0; rd < 2; rd++) {
#pragma unroll
      for (int half = 0; half < 2; half++) {
        const int ii = rd * 2 + half;
        const float* xiv = &xi[ii * 64];
#pragma unroll
        for (int r = 0; r < 8; r++) {
          const int e = t + r * 256;
          const int j = e >> 4, qp = e & 15, k = qp * 4;
          const float4 xj4 = *(const float4*)&xjs[j * 64 + k];
          uint2 o;
          o.x = pack_bf2(fabsf(xj4.x - xiv[k]), fabsf(xj4.y - xiv[k + 1]));
          o.y = pack_bf2(fabsf(xj4.z - xiv[k + 2]), fabsf(xj4.w - xiv[k + 3]));
          const uint32_t so = sw128((uint32_t)(j * 128 + qp * 8));
          *(uint2*)(smem + OFF_B + half * 16384 + so) = o;
        }
      }
      asm volatile("fence.proxy.async.shared::cta;" ::: "memory");
      __syncthreads();
      if (t == 0) {
#pragma unroll
        for (int half = 0; half < 2; half++) {
          const int ii = rd * 2 + half;
          const uint64_t bdesc = smem_desc(su + OFF_B + half * 16384);
#pragma unroll
          for (int ks = 0; ks < 4; ks++)
            mma_f16_ss(tmem + ii * 128, adesc + ks * 2, bdesc + ks * 2, IDESC,
                       ks > 0);
        }
        asm volatile(
            "tcgen05.commit.cta_group::1.mbarrier::arrive::one.shared::cluster."
            "b64 [%0];" ::"r"(su + OFF_MBAR)
            : "memory");
      }
      mbar_wait(su + OFF_MBAR, ph);
      ph ^= 1;
    }
    asm volatile("tcgen05.fence::after_thread_sync;" ::: "memory");

    // Epilogue: 4 chunks of 32 j-cols; T2 chunks double-buffered
#pragma unroll
    for (int c = 0; c < 4; c++) {
      const int cb = c & 1;
      if (c < 3) {
        const int nb = (c + 1) & 1;
#pragma unroll
        for (int r = 0; r < 4; r++) {
          const int e = t + r * 256;
          const int j = e >> 5, sg = e & 31;
          cp16(su + OFF_T2 + (uint32_t)(nb * 16384) +
                   (uint32_t)(j * 128 + sg * 4) * 4,
               &g_T2[(size_t)(j0 + (c + 1) * 32 + j) * HH + sg * 4]);
        }
        asm volatile("cp.async.commit_group;" ::: "memory");
      }
      float t2r[16];
#pragma unroll
      for (int r = 0; r < 16; r++)
        t2r[r] = t2c[cb * 4096 + (ch * 16 + r) * 128 + h];
#pragma unroll
      for (int ii = 0; ii < IB; ii++) {
        uint32_t Dr[16];
        LDTM_X16(Dr, tmem + ii * 128 + c * 32 + ch * 16);
        asm volatile("tcgen05.wait::ld.sync.aligned;" ::: "memory");
        float a = 0.f;
#pragma unroll
        for (int r = 0; r < 16; r++)
          a += fmaxf(__uint_as_float(Dr[r]) + t1v[ii] + t2r[r], 0.f);
        acc[ii] += a;
      }
      if (c < 3) {
        asm volatile("cp.async.wait_group 0;" ::: "memory");
        __syncthreads();
      }
    }
    asm volatile("tcgen05.fence::before_thread_sync;" ::: "memory");
    __syncthreads();  // D reads done before next tile's MMAs
  }

  // Combine col-halves and flush S
#pragma unroll
  for (int ii = 0; ii < IB; ii++) Sc[(ii * 2 + ch) * 128 + h] = acc[ii];
  __syncthreads();
  if (t < HH) {
#pragma unroll
    for (int ii = 0; ii < IB; ii++)
      atomicAdd(&g_S[(size_t)(i0 + ii) * HH + t],
                Sc[(ii * 2 + 0) * 128 + t] + Sc[(ii * 2 + 1) * 128 + t]);
  }
  __syncthreads();
  if (t == 0)
    asm volatile("mbarrier.inval.shared.b64 [%0];" ::"r"(su + OFF_MBAR)
                 : "memory");
  __syncthreads();
  if (w == 0)
    asm volatile("tcgen05.dealloc.cta_group::1.sync.aligned.b32 %0, %1;" ::"r"(
                     tmem),
                 "r"(512u));
#else
  // Fallback for the generic compute_103 PTX pass (correctness-only; the
  // sm_103a cubin above is what actually runs on GB300).
  const int t = threadIdx.x;
  const int h = t & 127;
  const int iio = t >> 7;
  const int ig = blockIdx.x >> 1, jh = blockIdx.x & 1;
  const int i0 = ig * IB;
  float wcol[DD];
  for (int d = 0; d < DD; d++) wcol[d] = W1[(size_t)(3 * DD + d) * HH + h];
  for (int io = iio; io < IB; io += 2) {
    const int i = i0 + io;
    const float t1 = g_T1[(size_t)i * HH + h];
    float s = 0.f;
    for (int j = jh * 512; j < jh * 512 + 512; j++) {
      float ta = 0.f;
      for (int d = 0; d < DD; d++)
        ta += fabsf(x[(size_t)i * DD + d] - x[(size_t)j * DD + d]) * wcol[d];
      s += fmaxf(ta + t1 + g_T2[(size_t)j * HH + h], 0.f);
    }
    atomicAdd(&g_S[(size_t)i * HH + h], s);
  }
#endif
}

// ---------------------------------------------------------------------------
// Kernel 3: head + layernorm per row
// ---------------------------------------------------------------------------
__global__ __launch_bounds__(HH) void head_kernel(
    const float* __restrict__ x, const float* __restrict__ W2,
    const float* __restrict__ b2, const float* __restrict__ Wa,
    const float* __restrict__ ba, const float* __restrict__ Wr,
    const float* __restrict__ br, const float* __restrict__ gamma,
    const float* __restrict__ beta, float* __restrict__ out) {
  __shared__ float S_s[HH], hm_s[HH], xi[DD];
  __shared__ float red[4];
  const int i = blockIdx.x;
  const int t = threadIdx.x;
  const int w = t >> 5, lane = t & 31;

  if (t < DD) xi[t] = x[i * DD + t];
  S_s[t] = g_S[(size_t)i * HH + t] * (1.0f / BB);
  __syncthreads();

  float acc = b2[t];
#pragma unroll 8
  for (int k = 0; k < HH; ++k) acc += S_s[k] * W2[k * HH + t];
  hm_s[t] = acc / g_tau[i];
  __syncthreads();

  float acc2 = ba[t];
#pragma unroll 8
  for (int k = 0; k < HH; ++k) acc2 += hm_s[k] * Wa[k * HH + t];
  const float hv = fmaxf(acc2, 0.f);
  float a3 = br[t];
#pragma unroll 8
  for (int d = 0; d < DD; ++d) a3 += xi[d] * Wr[d * HH + t];
  const float yv = hv + a3;

  float v = yv;
#pragma unroll
  for (int off = 16; off > 0; off >>= 1) v += __shfl_xor_sync(0xffffffffu, v, off);
  if (lane == 0) red[w] = v;
  __syncthreads();
  const float mu = (red[0] + red[1] + red[2] + red[3]) * (1.0f / HH);
  __syncthreads();
  const float dv = yv - mu;
  float v2 = dv * dv;
#pragma unroll
  for (int off = 16; off > 0; off >>= 1) v2 += __shfl_xor_sync(0xffffffffu, v2, off);
  if (lane == 0) red[w] = v2;
  __syncthreads();
  const float var = (red[0] + red[1] + red[2] + red[3]) * (1.0f / HH);

  out[(size_t)i * HH + t] = dv * rsqrtf(var + 1e-5f) * gamma[t] + beta[t];
}

// ---------------------------------------------------------------------------
// Inputs: 0:x 1:W1 2:b1 3:W2 4:b2 5:Wt 6:bt 7:Wa 8:ba 9:Wr 10:br 11:gamma 12:beta
// ---------------------------------------------------------------------------
extern "C" void kernel_launch(void* const* d_in, const int* in_sizes, int n_in,
                              void* d_out, int out_size) {
  const float* x     = (const float*)d_in[0];
  const float* W1    = (const float*)d_in[1];
  const float* b1    = (const float*)d_in[2];
  const float* W2    = (const float*)d_in[3];
  const float* b2    = (const float*)d_in[4];
  const float* Wt    = (const float*)d_in[5];
  const float* bt    = (const float*)d_in[6];
  const float* Wa    = (const float*)d_in[7];
  const float* ba    = (const float*)d_in[8];
  const float* Wr    = (const float*)d_in[9];
  const float* br    = (const float*)d_in[10];
  const float* gamma = (const float*)d_in[11];
  const float* beta  = (const float*)d_in[12];
  float* out = (float*)d_out;

  cudaFuncSetAttribute(pair_kernel, cudaFuncAttributeMaxDynamicSharedMemorySize,
                       SMEM_TOTAL);
  precompute_kernel<<<BB / 8, HH>>>(x, W1, b1, Wt, bt);
  pair_kernel<<<BB / IB * 2, THREADS, SMEM_TOTAL>>>(x, W1);
  head_kernel<<<BB, HH>>>(x, W2, b2, Wa, ba, Wr, br, gamma, beta, out);
}